// round 1
// baseline (speedup 1.0000x reference)
#include <cuda_runtime.h>
#include <math.h>

#define N_NODES 8192
#define IN_F    512
#define F       64
#define ALPHA   0.2f

// ---------------- scratch (no allocations allowed) ----------------
__device__ float g_h[N_NODES * F];   // h = x @ W   (2 MB, L2-resident)
__device__ float g_e1[N_NODES];
__device__ float g_e2[N_NODES];
__device__ float g_maxe2;

// ---------------- f32x2 packed-FMA helpers (sm_103a) ----------------
__device__ __forceinline__ unsigned long long pack2(float x, float y) {
    unsigned long long r;
    asm("mov.b64 %0, {%1, %2};" : "=l"(r) : "f"(x), "f"(y));
    return r;
}
__device__ __forceinline__ void ffma2(unsigned long long &d,
                                      unsigned long long a,
                                      unsigned long long b) {
    asm("fma.rn.f32x2 %0, %1, %2, %3;" : "=l"(d) : "l"(a), "l"(b), "l"(d));
}
__device__ __forceinline__ float2 unpack2(unsigned long long v) {
    float2 r;
    asm("mov.b64 {%0, %1}, %2;" : "=f"(r.x), "=f"(r.y) : "l"(v));
    return r;
}

// ---------------- kernel 1: h = x @ W  (fp32, f32x2 packed) ----------------
// grid 128, block 256. Each CTA: 64 rows x 64 cols. Thread: 4 rows x 4 cols.
__global__ __launch_bounds__(256) void gemm_h_kernel(const float* __restrict__ x,
                                                     const float* __restrict__ W) {
    __shared__ float xs[64 * 68];   // padded pitch 68 (16B-aligned rows)
    __shared__ float wsm[64 * 64];

    const int tid = threadIdx.x;
    const int i0  = blockIdx.x * 64;
    const int tf  = tid & 15;    // f-quad: f = tf*4 .. tf*4+3
    const int tg  = tid >> 4;    // row group: rows tg*4 .. tg*4+3

    unsigned long long acc[4][2];
#pragma unroll
    for (int r = 0; r < 4; r++) { acc[r][0] = 0ull; acc[r][1] = 0ull; }

    for (int kt = 0; kt < IN_F; kt += 64) {
#pragma unroll
        for (int q = tid; q < 1024; q += 256) {       // x tile 64x64
            int row = q >> 4, c4 = q & 15;
            float4 v = *(const float4*)(x + (long)(i0 + row) * IN_F + kt + c4 * 4);
            *(float4*)(xs + row * 68 + c4 * 4) = v;
        }
#pragma unroll
        for (int q = tid; q < 1024; q += 256) {       // W tile 64x64 (contiguous)
            float4 v = *(const float4*)(W + (long)kt * F + q * 4);
            *(float4*)(wsm + q * 4) = v;
        }
        __syncthreads();

#pragma unroll 8
        for (int kk = 0; kk < 64; kk++) {
            ulonglong2 wp = *(const ulonglong2*)(wsm + kk * 64 + tf * 4);
#pragma unroll
            for (int r = 0; r < 4; r++) {
                float xv = xs[(tg * 4 + r) * 68 + kk];
                unsigned long long x2 = pack2(xv, xv);
                ffma2(acc[r][0], x2, wp.x);
                ffma2(acc[r][1], x2, wp.y);
            }
        }
        __syncthreads();
    }

#pragma unroll
    for (int r = 0; r < 4; r++) {
        float2 lo = unpack2(acc[r][0]);
        float2 hi = unpack2(acc[r][1]);
        *(float4*)(g_h + (long)(i0 + tg * 4 + r) * F + tf * 4) =
            make_float4(lo.x, lo.y, hi.x, hi.y);
    }
}

// ---------------- kernel 2: e1 = h@a1, e2 = h@a2 (warp per row) ----------------
__global__ __launch_bounds__(256) void e12_kernel(const float* __restrict__ a) {
    const int tid  = threadIdx.x;
    const int lane = tid & 31;
    const int row  = blockIdx.x * 8 + (tid >> 5);

    float h0 = g_h[row * F + 2 * lane];
    float h1 = g_h[row * F + 2 * lane + 1];
    float p1 = h0 * a[2 * lane]      + h1 * a[2 * lane + 1];
    float p2 = h0 * a[64 + 2 * lane] + h1 * a[64 + 2 * lane + 1];
#pragma unroll
    for (int off = 16; off > 0; off >>= 1) {
        p1 += __shfl_xor_sync(0xffffffffu, p1, off);
        p2 += __shfl_xor_sync(0xffffffffu, p2, off);
    }
    if (lane == 0) { g_e1[row] = p1; g_e2[row] = p2; }
}

// ---------------- kernel 3: global max of e2 ----------------
__global__ __launch_bounds__(1024) void maxe2_kernel() {
    __shared__ float sm[32];
    const int tid = threadIdx.x;
    float v = -3.4e38f;
    for (int k = tid; k < N_NODES; k += 1024) v = fmaxf(v, g_e2[k]);
#pragma unroll
    for (int off = 16; off > 0; off >>= 1)
        v = fmaxf(v, __shfl_xor_sync(0xffffffffu, v, off));
    if ((tid & 31) == 0) sm[tid >> 5] = v;
    __syncthreads();
    if (tid < 32) {
        v = sm[tid];
#pragma unroll
        for (int off = 16; off > 0; off >>= 1)
            v = fmaxf(v, __shfl_xor_sync(0xffffffffu, v, off));
        if (tid == 0) g_maxe2 = v;
    }
}

// ---------------- kernel 4: fused masked softmax + attn@h + ELU ----------------
// grid 128, block 256. CTA: 64 output rows, loops over all 8192 j in tiles of 64.
// Static per-row shift m_i = lrelu(e1_i + max(e2)) >= every row logit, so a
// single pass computes Z_i and acc_i simultaneously (no online rescale).
__global__ __launch_bounds__(256) void aggregate_kernel(const int* __restrict__ adj,
                                                        float* __restrict__ out) {
    __shared__ float ws[64 * 68];   // w tile, pitch 68 (bank-safe, 16B rows)
    __shared__ float hs[64 * 64];   // h tile [j][f]
    __shared__ float e1s[64];
    __shared__ float ms[64];
    __shared__ float zs[64];

    const int tid = threadIdx.x;
    const int i0  = blockIdx.x * 64;
    const float maxe2 = g_maxe2;

    if (tid < 64) {
        float e1v = g_e1[i0 + tid];
        e1s[tid]  = e1v;
        float s   = e1v + maxe2;
        ms[tid]   = fmaxf(s, ALPHA * s);   // leaky_relu
    }

    float zacc = 0.0f;
    unsigned long long acc[8];
#pragma unroll
    for (int u = 0; u < 8; u++) acc[u] = 0ull;

    const int irow = tid >> 2;          // 0..63  (4 threads per row)
    const int f0   = (tid & 3) * 16;    // 16 f-columns = 8 f32x2 per thread
    __syncthreads();

    for (int jt = 0; jt < N_NODES / 64; jt++) {
        const int j0 = jt * 64;

        // phase a: w tile = adj ? exp(lrelu(e1+e2) - m) : 0   (adj streamed)
#pragma unroll
        for (int p = tid; p < 4096; p += 256) {
            int ii = p >> 6, jj = p & 63;
            int   av  = __ldcs(adj + (long)(i0 + ii) * N_NODES + j0 + jj);
            float e2v = __ldg(g_e2 + j0 + jj);
            float s   = e1s[ii] + e2v;
            float l   = fmaxf(s, ALPHA * s);
            float w   = (av > 0) ? __expf(l - ms[ii]) : 0.0f;
            ws[ii * 68 + jj] = w;
        }
        // phase b: h tile (L2-resident)
#pragma unroll
        for (int q = tid; q < 1024; q += 256) {
            int jj = q >> 4, c4 = q & 15;
            float4 v = *(const float4*)(g_h + (long)(j0 + jj) * F + c4 * 4);
            *(float4*)(hs + jj * 64 + c4 * 4) = v;
        }
        __syncthreads();

        // phase z: Z row-sums (threads 0..63, one row each)
        if (tid < 64) {
            float zz = 0.0f;
#pragma unroll
            for (int jj = 0; jj < 64; jj += 4) {
                float4 wq = *(const float4*)(ws + tid * 68 + jj);
                zz += (wq.x + wq.y) + (wq.z + wq.w);
            }
            zacc += zz;
        }

        // phase c: acc[irow, f0..f0+15] += w[irow][j] * h[j][f]   (f32x2)
#pragma unroll 4
        for (int jj4 = 0; jj4 < 64; jj4 += 4) {
            float4 w4 = *(const float4*)(ws + irow * 68 + jj4);
#pragma unroll
            for (int u = 0; u < 4; u++) {
                float wv = ((const float*)&w4)[u];
                unsigned long long w2 = pack2(wv, wv);
                const ulonglong2* hp = (const ulonglong2*)(hs + (jj4 + u) * 64 + f0);
                ulonglong2 p0 = hp[0], p1 = hp[1], p2 = hp[2], p3 = hp[3];
                ffma2(acc[0], w2, p0.x); ffma2(acc[1], w2, p0.y);
                ffma2(acc[2], w2, p1.x); ffma2(acc[3], w2, p1.y);
                ffma2(acc[4], w2, p2.x); ffma2(acc[5], w2, p2.y);
                ffma2(acc[6], w2, p3.x); ffma2(acc[7], w2, p3.y);
            }
        }
        __syncthreads();
    }

    if (tid < 64) zs[tid] = zacc;
    __syncthreads();

    const float zinv = 1.0f / zs[irow];
    float vals[16];
#pragma unroll
    for (int u = 0; u < 8; u++) {
        float2 v  = unpack2(acc[u]);
        float o0 = v.x * zinv, o1 = v.y * zinv;
        vals[2 * u]     = (o0 > 0.0f) ? o0 : expm1f(o0);   // ELU
        vals[2 * u + 1] = (o1 > 0.0f) ? o1 : expm1f(o1);
    }
    float* op = out + (long)(i0 + irow) * F + f0;
#pragma unroll
    for (int q = 0; q < 4; q++)
        *(float4*)(op + q * 4) =
            make_float4(vals[4 * q], vals[4 * q + 1], vals[4 * q + 2], vals[4 * q + 3]);
}

// ---------------- launch ----------------
extern "C" void kernel_launch(void* const* d_in, const int* in_sizes, int n_in,
                              void* d_out, int out_size) {
    const float* x   = (const float*)d_in[0];
    const int*   adj = (const int*)  d_in[1];
    const float* W   = (const float*)d_in[2];
    const float* a   = (const float*)d_in[3];
    float* out = (float*)d_out;

    gemm_h_kernel<<<N_NODES / 64, 256>>>(x, W);
    e12_kernel<<<N_NODES / 8, 256>>>(a);
    maxe2_kernel<<<1, 1024>>>();
    aggregate_kernel<<<N_NODES / 64, 256>>>(adj, out);
}

// round 2
// speedup vs baseline: 1.1537x; 1.1537x over previous
#include <cuda_runtime.h>
#include <math.h>

#define N_NODES 8192
#define IN_F    512
#define F       64
#define ALPHA   0.2f
#define TI      32     // rows per CTA (aggregate)
#define TJ      64     // j per tile
#define NTILE   (N_NODES / TJ)

// ---------------- scratch (no allocations allowed) ----------------
__device__ float g_h[N_NODES * F];   // h = x @ W   (2 MB, L2-resident)
__device__ float g_e1[N_NODES];
__device__ float g_e2[N_NODES];
__device__ float g_maxe2;

// ---------------- f32x2 packed-FMA helpers (sm_103a) ----------------
__device__ __forceinline__ unsigned long long pack2(float x, float y) {
    unsigned long long r;
    asm("mov.b64 %0, {%1, %2};" : "=l"(r) : "f"(x), "f"(y));
    return r;
}
__device__ __forceinline__ void ffma2(unsigned long long &d,
                                      unsigned long long a,
                                      unsigned long long b) {
    asm("fma.rn.f32x2 %0, %1, %2, %3;" : "=l"(d) : "l"(a), "l"(b), "l"(d));
}
__device__ __forceinline__ float2 unpack2(unsigned long long v) {
    float2 r;
    asm("mov.b64 {%0, %1}, %2;" : "=f"(r.x), "=f"(r.y) : "l"(v));
    return r;
}

// ---------------- kernel 1: h = x @ W  (fp32, f32x2 packed) ----------------
__global__ __launch_bounds__(256) void gemm_h_kernel(const float* __restrict__ x,
                                                     const float* __restrict__ W) {
    __shared__ float xs[64 * 68];
    __shared__ float wsm[64 * 64];

    const int tid = threadIdx.x;
    const int i0  = blockIdx.x * 64;
    const int tf  = tid & 15;
    const int tg  = tid >> 4;

    unsigned long long acc[4][2];
#pragma unroll
    for (int r = 0; r < 4; r++) { acc[r][0] = 0ull; acc[r][1] = 0ull; }

    for (int kt = 0; kt < IN_F; kt += 64) {
#pragma unroll
        for (int q = tid; q < 1024; q += 256) {
            int row = q >> 4, c4 = q & 15;
            float4 v = *(const float4*)(x + (long)(i0 + row) * IN_F + kt + c4 * 4);
            *(float4*)(xs + row * 68 + c4 * 4) = v;
        }
#pragma unroll
        for (int q = tid; q < 1024; q += 256) {
            float4 v = *(const float4*)(W + (long)kt * F + q * 4);
            *(float4*)(wsm + q * 4) = v;
        }
        __syncthreads();

#pragma unroll 8
        for (int kk = 0; kk < 64; kk++) {
            ulonglong2 wp = *(const ulonglong2*)(wsm + kk * 64 + tf * 4);
#pragma unroll
            for (int r = 0; r < 4; r++) {
                float xv = xs[(tg * 4 + r) * 68 + kk];
                unsigned long long x2 = pack2(xv, xv);
                ffma2(acc[r][0], x2, wp.x);
                ffma2(acc[r][1], x2, wp.y);
            }
        }
        __syncthreads();
    }

#pragma unroll
    for (int r = 0; r < 4; r++) {
        float2 lo = unpack2(acc[r][0]);
        float2 hi = unpack2(acc[r][1]);
        *(float4*)(g_h + (long)(i0 + tg * 4 + r) * F + tf * 4) =
            make_float4(lo.x, lo.y, hi.x, hi.y);
    }
}

// ---------------- kernel 2: e1 = h@a1, e2 = h@a2 (warp per row) ----------------
__global__ __launch_bounds__(256) void e12_kernel(const float* __restrict__ a) {
    const int tid  = threadIdx.x;
    const int lane = tid & 31;
    const int row  = blockIdx.x * 8 + (tid >> 5);

    float h0 = g_h[row * F + 2 * lane];
    float h1 = g_h[row * F + 2 * lane + 1];
    float p1 = h0 * a[2 * lane]      + h1 * a[2 * lane + 1];
    float p2 = h0 * a[64 + 2 * lane] + h1 * a[64 + 2 * lane + 1];
#pragma unroll
    for (int off = 16; off > 0; off >>= 1) {
        p1 += __shfl_xor_sync(0xffffffffu, p1, off);
        p2 += __shfl_xor_sync(0xffffffffu, p2, off);
    }
    if (lane == 0) { g_e1[row] = p1; g_e2[row] = p2; }
}

// ---------------- kernel 3: global max of e2 ----------------
__global__ __launch_bounds__(1024) void maxe2_kernel() {
    __shared__ float sm[32];
    const int tid = threadIdx.x;
    float v = -3.4e38f;
    for (int k = tid; k < N_NODES; k += 1024) v = fmaxf(v, g_e2[k]);
#pragma unroll
    for (int off = 16; off > 0; off >>= 1)
        v = fmaxf(v, __shfl_xor_sync(0xffffffffu, v, off));
    if ((tid & 31) == 0) sm[tid >> 5] = v;
    __syncthreads();
    if (tid < 32) {
        v = sm[tid];
#pragma unroll
        for (int off = 16; off > 0; off >>= 1)
            v = fmaxf(v, __shfl_xor_sync(0xffffffffu, v, off));
        if (tid == 0) g_maxe2 = v;
    }
}

// ---------------- kernel 4: fused masked softmax + attn@h + ELU ----------------
// 256 CTAs x 256 threads, 2 CTAs/SM. Per CTA: TI=32 rows, loops over 128 j-tiles
// of TJ=64. Register prefetch (adj, e2, h) + double-buffered smem, one barrier
// per tile. Thread (ii = tid>>3, k = tid&7):
//   store phase: w for row ii at j = j0 + k + 8u, u=0..7 (duplicated f32x2 pairs)
//   compute phase: row ii, f-columns f0 = k*8 .. k*8+7  (4 packed accumulators)
#define WPITCH 132   // floats per ws2 row (2*TJ + 4 pad)

__global__ __launch_bounds__(256, 2) void aggregate_kernel(const int* __restrict__ adj,
                                                           float* __restrict__ out) {
    __shared__ float ws2[2][TI * WPITCH];  // duplicated weights, double buffered
    __shared__ float hs[2][TJ * F];        // h tile, double buffered
    __shared__ float e1s[TI];
    __shared__ float ms[TI];

    const int tid = threadIdx.x;
    const int i0  = blockIdx.x * TI;
    const int ii  = tid >> 3;     // row 0..31
    const int k   = tid & 7;      // j-residue / f-group
    const int f0  = k * 8;

    if (tid < TI) {
        float e1v = g_e1[i0 + tid];
        e1s[tid]  = e1v;
        float s   = e1v + g_maxe2;
        ms[tid]   = fmaxf(s, ALPHA * s);
    }

    const int* adjrow = adj + (long)(i0 + ii) * N_NODES + k;

    int    adjv[8];
    float  e2r[8];
    float4 hreg[4];

    // prefetch tile 0
#pragma unroll
    for (int u = 0; u < 8; u++) {
        adjv[u] = __ldcs(adjrow + 8 * u);
        e2r[u]  = __ldg(g_e2 + k + 8 * u);
    }
#pragma unroll
    for (int q = 0; q < 4; q++) {
        int p = tid + q * 256;
        int jj = p >> 4, c4 = p & 15;
        hreg[q] = *(const float4*)(g_h + (long)jj * F + c4 * 4);
    }

    float zacc = 0.0f;
    unsigned long long acc[4] = {0ull, 0ull, 0ull, 0ull};

    __syncthreads();

    for (int jt = 0; jt < NTILE; jt++) {
        const int buf = jt & 1;

        // ---- store phase: w tile (duplicated pairs) + z partial, h tile ----
        const float e1v = e1s[ii];
        const float mv  = ms[ii];
#pragma unroll
        for (int u = 0; u < 8; u++) {
            float s = e1v + e2r[u];
            float l = fmaxf(s, ALPHA * s);
            float w = (adjv[u] > 0) ? __expf(l - mv) : 0.0f;
            zacc += w;
            *(float2*)&ws2[buf][ii * WPITCH + 2 * (k + 8 * u)] = make_float2(w, w);
        }
#pragma unroll
        for (int q = 0; q < 4; q++) {
            int p = tid + q * 256;
            int jj = p >> 4, c4 = p & 15;
            *(float4*)&hs[buf][jj * F + c4 * 4] = hreg[q];
        }
        __syncthreads();

        // ---- prefetch tile jt+1 (LDGs in flight under compute) ----
        if (jt + 1 < NTILE) {
            const int j0n = (jt + 1) * TJ;
#pragma unroll
            for (int u = 0; u < 8; u++) {
                adjv[u] = __ldcs(adjrow + j0n + 8 * u);
                e2r[u]  = __ldg(g_e2 + j0n + k + 8 * u);
            }
#pragma unroll
            for (int q = 0; q < 4; q++) {
                int p = tid + q * 256;
                int jj = p >> 4, c4 = p & 15;
                hreg[q] = *(const float4*)(g_h + (long)(j0n + jj) * F + c4 * 4);
            }
        }

        // ---- compute phase: acc[ii, f0..f0+7] += w * h ----
        const float* wr = &ws2[buf][ii * WPITCH];
        const float* hb = &hs[buf][f0];
#pragma unroll 4
        for (int j2 = 0; j2 < TJ / 2; j2++) {
            ulonglong2 wp = *(const ulonglong2*)(wr + 4 * j2);
            ulonglong2 h0 = *(const ulonglong2*)(hb + (2 * j2) * F);
            ulonglong2 h1 = *(const ulonglong2*)(hb + (2 * j2) * F + 4);
            ulonglong2 h2 = *(const ulonglong2*)(hb + (2 * j2 + 1) * F);
            ulonglong2 h3 = *(const ulonglong2*)(hb + (2 * j2 + 1) * F + 4);
            ffma2(acc[0], wp.x, h0.x); ffma2(acc[1], wp.x, h0.y);
            ffma2(acc[2], wp.x, h1.x); ffma2(acc[3], wp.x, h1.y);
            ffma2(acc[0], wp.y, h2.x); ffma2(acc[1], wp.y, h2.y);
            ffma2(acc[2], wp.y, h3.x); ffma2(acc[3], wp.y, h3.y);
        }
    }

    // ---- Z reduce across the 8 threads of each row (xor: all lanes get sum) ----
#pragma unroll
    for (int off = 4; off > 0; off >>= 1)
        zacc += __shfl_xor_sync(0xffffffffu, zacc, off);
    const float zinv = 1.0f / zacc;

    float vals[8];
#pragma unroll
    for (int u = 0; u < 4; u++) {
        float2 v  = unpack2(acc[u]);
        float o0 = v.x * zinv, o1 = v.y * zinv;
        vals[2 * u]     = (o0 > 0.0f) ? o0 : expm1f(o0);
        vals[2 * u + 1] = (o1 > 0.0f) ? o1 : expm1f(o1);
    }
    float* op = out + (long)(i0 + ii) * F + f0;
    *(float4*)(op)     = make_float4(vals[0], vals[1], vals[2], vals[3]);
    *(float4*)(op + 4) = make_float4(vals[4], vals[5], vals[6], vals[7]);
}

// ---------------- launch ----------------
extern "C" void kernel_launch(void* const* d_in, const int* in_sizes, int n_in,
                              void* d_out, int out_size) {
    const float* x   = (const float*)d_in[0];
    const int*   adj = (const int*)  d_in[1];
    const float* W   = (const float*)d_in[2];
    const float* a   = (const float*)d_in[3];
    float* out = (float*)d_out;

    gemm_h_kernel<<<N_NODES / 64, 256>>>(x, W);
    e12_kernel<<<N_NODES / 8, 256>>>(a);
    maxe2_kernel<<<1, 1024>>>();
    aggregate_kernel<<<N_NODES / TI, 256>>>(adj, out);
}

// round 3
// speedup vs baseline: 4.3835x; 3.7996x over previous
#include <cuda_runtime.h>
#include <math.h>

#define N_NODES 8192
#define IN_F    512
#define F       64
#define ALPHA   0.2f

#define S_SPLIT 8              // j-splits across grid
#define TI      256            // rows per CTA
#define TJ      32             // j per tile
#define JRANGE  (N_NODES / S_SPLIT)   // 1024
#define NTILE   (JRANGE / TJ)         // 32
#define WP      260            // ws row pitch (floats), 16B-aligned rows

typedef unsigned long long ull;

// ---------------- scratch (no allocations allowed) ----------------
__device__ float g_h[N_NODES * F];                 // 2 MB
__device__ float g_e1[N_NODES];
__device__ float g_e2[N_NODES];
__device__ float g_maxe2;
__device__ float g_part[(long)S_SPLIT * N_NODES * F];  // 16 MB partial acc
__device__ float g_zpart[S_SPLIT * N_NODES];           // partial Z

// ---------------- f32x2 helpers ----------------
__device__ __forceinline__ ull pack2(float x, float y) {
    ull r; asm("mov.b64 %0, {%1, %2};" : "=l"(r) : "f"(x), "f"(y)); return r;
}
__device__ __forceinline__ void ffma2(ull &d, ull a, ull b) {
    asm("fma.rn.f32x2 %0, %1, %2, %3;" : "=l"(d) : "l"(a), "l"(b), "l"(d));
}
__device__ __forceinline__ float2 unpack2(ull v) {
    float2 r; asm("mov.b64 {%0, %1}, %2;" : "=f"(r.x), "=f"(r.y) : "l"(v)); return r;
}

// ---------------- kernel 1: h = x @ W ----------------
__global__ __launch_bounds__(256) void gemm_h_kernel(const float* __restrict__ x,
                                                     const float* __restrict__ W) {
    __shared__ float xs[64 * 68];
    __shared__ float wsm[64 * 64];

    const int tid = threadIdx.x;
    const int i0  = blockIdx.x * 64;
    const int tf  = tid & 15;
    const int tg  = tid >> 4;

    ull acc[4][2];
#pragma unroll
    for (int r = 0; r < 4; r++) { acc[r][0] = 0ull; acc[r][1] = 0ull; }

    for (int kt = 0; kt < IN_F; kt += 64) {
#pragma unroll
        for (int q = tid; q < 1024; q += 256) {
            int row = q >> 4, c4 = q & 15;
            float4 v = *(const float4*)(x + (long)(i0 + row) * IN_F + kt + c4 * 4);
            *(float4*)(xs + row * 68 + c4 * 4) = v;
        }
#pragma unroll
        for (int q = tid; q < 1024; q += 256) {
            float4 v = *(const float4*)(W + (long)kt * F + q * 4);
            *(float4*)(wsm + q * 4) = v;
        }
        __syncthreads();
#pragma unroll 8
        for (int kk = 0; kk < 64; kk++) {
            ulonglong2 wp = *(const ulonglong2*)(wsm + kk * 64 + tf * 4);
#pragma unroll
            for (int r = 0; r < 4; r++) {
                float xv = xs[(tg * 4 + r) * 68 + kk];
                ull x2 = pack2(xv, xv);
                ffma2(acc[r][0], x2, wp.x);
                ffma2(acc[r][1], x2, wp.y);
            }
        }
        __syncthreads();
    }
#pragma unroll
    for (int r = 0; r < 4; r++) {
        float2 lo = unpack2(acc[r][0]);
        float2 hi = unpack2(acc[r][1]);
        *(float4*)(g_h + (long)(i0 + tg * 4 + r) * F + tf * 4) =
            make_float4(lo.x, lo.y, hi.x, hi.y);
    }
}

// ---------------- kernel 2: e1, e2 ----------------
__global__ __launch_bounds__(256) void e12_kernel(const float* __restrict__ a) {
    const int tid  = threadIdx.x;
    const int lane = tid & 31;
    const int row  = blockIdx.x * 8 + (tid >> 5);

    float h0 = g_h[row * F + 2 * lane];
    float h1 = g_h[row * F + 2 * lane + 1];
    float p1 = h0 * a[2 * lane]      + h1 * a[2 * lane + 1];
    float p2 = h0 * a[64 + 2 * lane] + h1 * a[64 + 2 * lane + 1];
#pragma unroll
    for (int off = 16; off > 0; off >>= 1) {
        p1 += __shfl_xor_sync(0xffffffffu, p1, off);
        p2 += __shfl_xor_sync(0xffffffffu, p2, off);
    }
    if (lane == 0) { g_e1[row] = p1; g_e2[row] = p2; }
}

// ---------------- kernel 3: global max of e2 ----------------
__global__ __launch_bounds__(1024) void maxe2_kernel() {
    __shared__ float sm[32];
    const int tid = threadIdx.x;
    float v = -3.4e38f;
    for (int k = tid; k < N_NODES; k += 1024) v = fmaxf(v, g_e2[k]);
#pragma unroll
    for (int off = 16; off > 0; off >>= 1)
        v = fmaxf(v, __shfl_xor_sync(0xffffffffu, v, off));
    if ((tid & 31) == 0) sm[tid >> 5] = v;
    __syncthreads();
    if (tid < 32) {
        v = sm[tid];
#pragma unroll
        for (int off = 16; off > 0; off >>= 1)
            v = fmaxf(v, __shfl_xor_sync(0xffffffffu, v, off));
        if (tid == 0) g_maxe2 = v;
    }
}

// ---------------- kernel 4: partial masked-softmax aggregate ----------------
// grid = 32 row-blocks x 8 j-splits = 256 CTAs, 256 threads, 2 CTAs/SM.
// CTA: TI=256 rows x JRANGE=1024 j, in 32 tiles of TJ=32.
// Store phase: thread (a = tid&31 -> j = j0+a; b = tid>>5 -> rows b*32..+31)
//   coalesced adj loads, w written to ws[j][i] (transposed, scalar).
// Compute phase: thread (rg = tid>>3 -> rows rg*8..+7; g = tid&7 -> f = g*8..+7)
//   per j: 2 LDS.128 (w, 8 rows) + 2 LDS.128 (h, 8 cols) -> 32 ffma2 + 4 z-ffma2.
__global__ __launch_bounds__(256, 2) void aggregate_kernel(const int* __restrict__ adj) {
    extern __shared__ float smem[];
    float*  ws0 = smem;                          // 2 * TJ * WP
    float*  hs0 = smem + 2 * TJ * WP;            // 2 * TJ * 64
    float2* rc  = (float2*)(smem + 2 * TJ * WP + 2 * TJ * 64);  // TI float2

    const int tid = threadIdx.x;
    const int s   = blockIdx.x & (S_SPLIT - 1);
    const int i0  = (blockIdx.x >> 3) * TI;
    const int jbase = s * JRANGE;

    if (tid < TI) {
        float e1v = g_e1[i0 + tid];
        float m   = e1v + g_maxe2;
        m = fmaxf(m, ALPHA * m);
        rc[tid] = make_float2(e1v, m);
    }

    const int a  = tid & 31;
    const int b  = tid >> 5;
    const int g  = tid & 7;
    const int rg = tid >> 3;

    ull acc[8][4];
#pragma unroll
    for (int r = 0; r < 8; r++)
#pragma unroll
        for (int c = 0; c < 4; c++) acc[r][c] = 0ull;
    ull z2[4] = {0ull, 0ull, 0ull, 0ull};
    const ull one2 = pack2(1.0f, 1.0f);

    const int* aprow = adj + (long)(i0 + b * 32) * N_NODES + jbase + a;

    __syncthreads();

    for (int jt = 0; jt < NTILE; jt++) {
        const int buf = jt & 1;
        const int j0  = jbase + jt * TJ;
        float* ws  = ws0 + buf * (TJ * WP);
        float* hsb = hs0 + buf * (TJ * 64);

        // ---- h tile: 8 floats per thread, coalesced ----
        {
            const int jj = tid >> 3;
            const int f  = (tid & 7) * 8;
            const float* hp = g_h + (long)(j0 + jj) * F + f;
            float4 v0 = *(const float4*)(hp);
            float4 v1 = *(const float4*)(hp + 4);
            *(float4*)(hsb + jj * F + f)     = v0;
            *(float4*)(hsb + jj * F + f + 4) = v1;
        }

        // ---- w tile: 32 rows per thread at column j0+a, batched LDG ----
        {
            const float e2v = __ldg(g_e2 + j0 + a);
            const int*  ap  = aprow + jt * TJ;
#pragma unroll
            for (int qb = 0; qb < 32; qb += 8) {
                int av[8];
#pragma unroll
                for (int u = 0; u < 8; u++)
                    av[u] = __ldcs(ap + (long)(qb + u) * N_NODES);
#pragma unroll
                for (int u = 0; u < 8; u++) {
                    int i = b * 32 + qb + u;
                    float2 c = rc[i];
                    float sv = c.x + e2v;
                    float l  = fmaxf(sv, ALPHA * sv);
                    ws[a * WP + i] = (av[u] > 0) ? __expf(l - c.y) : 0.0f;
                }
            }
        }
        __syncthreads();

        // ---- compute: 8 rows x 8 f-cols per thread ----
        const float* wr = ws  + rg * 8;
        const float* hb = hsb + g * 8;
#pragma unroll 2
        for (int j = 0; j < TJ; j++) {
            float4 w0 = *(const float4*)(wr + j * WP);
            float4 w1 = *(const float4*)(wr + j * WP + 4);
            ulonglong2 h0 = *(const ulonglong2*)(hb + j * F);
            ulonglong2 h1 = *(const ulonglong2*)(hb + j * F + 4);

            // Z partials: reinterpret w quads as f32x2 pairs
            ffma2(z2[0], ((const ull*)&w0)[0], one2);
            ffma2(z2[1], ((const ull*)&w0)[1], one2);
            ffma2(z2[2], ((const ull*)&w1)[0], one2);
            ffma2(z2[3], ((const ull*)&w1)[1], one2);

            float wv[8] = {w0.x, w0.y, w0.z, w0.w, w1.x, w1.y, w1.z, w1.w};
#pragma unroll
            for (int r = 0; r < 8; r++) {
                ull w2 = pack2(wv[r], wv[r]);
                ffma2(acc[r][0], w2, h0.x);
                ffma2(acc[r][1], w2, h0.y);
                ffma2(acc[r][2], w2, h1.x);
                ffma2(acc[r][3], w2, h1.y);
            }
        }
        // next store phase writes buf^1: safe, all threads past this tile's sync
        if (jt + 1 < NTILE) __syncthreads();
    }

    // ---- write partials ----
    float* pp = g_part + ((long)s * N_NODES + i0 + rg * 8) * F + g * 8;
#pragma unroll
    for (int r = 0; r < 8; r++) {
        float2 v0 = unpack2(acc[r][0]);
        float2 v1 = unpack2(acc[r][1]);
        float2 v2 = unpack2(acc[r][2]);
        float2 v3 = unpack2(acc[r][3]);
        *(float4*)(pp + (long)r * F)     = make_float4(v0.x, v0.y, v1.x, v1.y);
        *(float4*)(pp + (long)r * F + 4) = make_float4(v2.x, v2.y, v3.x, v3.y);
    }
    if (g == 0) {
#pragma unroll
        for (int q = 0; q < 4; q++) {
            float2 z = unpack2(z2[q]);
            g_zpart[s * N_NODES + i0 + rg * 8 + 2 * q]     = z.x;
            g_zpart[s * N_NODES + i0 + rg * 8 + 2 * q + 1] = z.y;
        }
    }
}

// ---------------- kernel 5: combine partials, normalize, ELU ----------------
__global__ __launch_bounds__(256) void combine_kernel(float* __restrict__ out) {
    const int t = blockIdx.x * 256 + threadIdx.x;   // 0 .. N*F-1
    const int i = t >> 6;
    float acc = 0.0f, z = 0.0f;
#pragma unroll
    for (int s = 0; s < S_SPLIT; s++) {
        acc += g_part[(long)s * N_NODES * F + t];
        z   += g_zpart[s * N_NODES + i];
    }
    float o = acc / z;
    out[t] = (o > 0.0f) ? o : expm1f(o);
}

// ---------------- launch ----------------
extern "C" void kernel_launch(void* const* d_in, const int* in_sizes, int n_in,
                              void* d_out, int out_size) {
    const float* x   = (const float*)d_in[0];
    const int*   adj = (const int*)  d_in[1];
    const float* W   = (const float*)d_in[2];
    const float* a   = (const float*)d_in[3];
    float* out = (float*)d_out;

    const int smem_agg = (2 * TJ * WP + 2 * TJ * 64 + 2 * TI) * 4;  // 84992 B
    static int attr_done = 0;
    if (!attr_done) {
        cudaFuncSetAttribute(aggregate_kernel,
                             cudaFuncAttributeMaxDynamicSharedMemorySize, smem_agg);
        attr_done = 1;
    }

    gemm_h_kernel<<<N_NODES / 64, 256>>>(x, W);
    e12_kernel<<<N_NODES / 8, 256>>>(a);
    maxe2_kernel<<<1, 1024>>>();
    aggregate_kernel<<<(N_NODES / TI) * S_SPLIT, 256, smem_agg>>>(adj);
    combine_kernel<<<(N_NODES * F) / 256, 256>>>(out);
}

// round 6
// speedup vs baseline: 10.8017x; 2.4642x over previous
#include <cuda_runtime.h>
#include <cuda_bf16.h>
#include <math.h>
#include <stdint.h>

#define NND    8192
#define IN_F   512
#define F      64
#define ALPHA  0.2f

#define JSPLIT 4
#define KRANGE (NND / JSPLIT)      // 2048 j per CTA
#define KSTEPS (KRANGE / 16)       // 128
#define NJBLK  (NND / 16)          // 512

typedef unsigned long long ull;
typedef unsigned int u32;

// ---------------- device scratch ----------------
__device__ float  g_h[NND * F];                    // 2 MB
__device__ float  g_e1[NND];
__device__ float  g_e2[NND];
__device__ float  g_maxe2;
__device__ float2 g_fBD[NND];                      // per-j (Q_j, D_j)
__device__ uint4  g_hB[NJBLK * 8 * 32];            // B frags {b0h,b1h,b0l,b1l}, 2 MB
__device__ float  g_part[(long)JSPLIT * NND * F];  // 8 MB partials
__device__ float  g_zpart[JSPLIT * NND];

// ---------------- helpers ----------------
__device__ __forceinline__ ull pack2(float x, float y) {
    ull r; asm("mov.b64 %0, {%1, %2};" : "=l"(r) : "f"(x), "f"(y)); return r;
}
__device__ __forceinline__ void ffma2(ull &d, ull a, ull b) {
    asm("fma.rn.f32x2 %0, %1, %2, %3;" : "=l"(d) : "l"(a), "l"(b), "l"(d));
}
__device__ __forceinline__ float2 unpack2(ull v) {
    float2 r; asm("mov.b64 {%0, %1}, %2;" : "=f"(r.x), "=f"(r.y) : "l"(v)); return r;
}
// pack bf16x2: lo -> low half (even k), hi -> high half (odd k)
__device__ __forceinline__ u32 cvt2(float lo, float hi) {
    u32 r; asm("cvt.rn.bf16x2.f32 %0, %1, %2;" : "=r"(r) : "f"(hi), "f"(lo)); return r;
}
__device__ __forceinline__ float bflo(u32 p) { return __uint_as_float(p << 16); }
__device__ __forceinline__ float bfhi(u32 p) { return __uint_as_float(p & 0xFFFF0000u); }

// m16n8k16 bf16 MMA, f32 accumulate (base PTX, valid for compute_103)
__device__ __forceinline__ void mma_bf16(float* d,
                                         u32 a0, u32 a1, u32 a2, u32 a3,
                                         u32 b0, u32 b1) {
    asm volatile(
        "mma.sync.aligned.m16n8k16.row.col.f32.bf16.bf16.f32 "
        "{%0,%1,%2,%3}, {%4,%5,%6,%7}, {%8,%9}, {%0,%1,%2,%3};"
        : "+f"(d[0]), "+f"(d[1]), "+f"(d[2]), "+f"(d[3])
        : "r"(a0), "r"(a1), "r"(a2), "r"(a3), "r"(b0), "r"(b1));
}

// ---------------- kernel 1: h = x @ W (fp32 f32x2 SIMT) ----------------
__global__ __launch_bounds__(256) void gemm_h_kernel(const float* __restrict__ x,
                                                     const float* __restrict__ W) {
    __shared__ float xs[64 * 68];
    __shared__ float wsm[64 * 64];

    const int tid = threadIdx.x;
    const int i0  = blockIdx.x * 64;
    const int tf  = tid & 15;
    const int tg  = tid >> 4;

    ull acc[4][2];
#pragma unroll
    for (int r = 0; r < 4; r++) { acc[r][0] = 0ull; acc[r][1] = 0ull; }

    for (int kt = 0; kt < IN_F; kt += 64) {
#pragma unroll
        for (int q = tid; q < 1024; q += 256) {
            int row = q >> 4, c4 = q & 15;
            float4 v = *(const float4*)(x + (long)(i0 + row) * IN_F + kt + c4 * 4);
            *(float4*)(xs + row * 68 + c4 * 4) = v;
        }
#pragma unroll
        for (int q = tid; q < 1024; q += 256) {
            float4 v = *(const float4*)(W + (long)kt * F + q * 4);
            *(float4*)(wsm + q * 4) = v;
        }
        __syncthreads();
#pragma unroll 8
        for (int kk = 0; kk < 64; kk++) {
            ulonglong2 wp = *(const ulonglong2*)(wsm + kk * 64 + tf * 4);
#pragma unroll
            for (int r = 0; r < 4; r++) {
                float xv = xs[(tg * 4 + r) * 68 + kk];
                ull x2 = pack2(xv, xv);
                ffma2(acc[r][0], x2, wp.x);
                ffma2(acc[r][1], x2, wp.y);
            }
        }
        __syncthreads();
    }
#pragma unroll
    for (int r = 0; r < 4; r++) {
        float2 lo = unpack2(acc[r][0]);
        float2 hi = unpack2(acc[r][1]);
        *(float4*)(g_h + (long)(i0 + tg * 4 + r) * F + tf * 4) =
            make_float4(lo.x, lo.y, hi.x, hi.y);
    }
}

// ---------------- kernel 2: e1, e2 ----------------
__global__ __launch_bounds__(256) void e12_kernel(const float* __restrict__ a) {
    const int tid  = threadIdx.x;
    const int lane = tid & 31;
    const int row  = blockIdx.x * 8 + (tid >> 5);

    float h0 = g_h[row * F + 2 * lane];
    float h1 = g_h[row * F + 2 * lane + 1];
    float p1 = h0 * a[2 * lane]      + h1 * a[2 * lane + 1];
    float p2 = h0 * a[64 + 2 * lane] + h1 * a[64 + 2 * lane + 1];
#pragma unroll
    for (int off = 16; off > 0; off >>= 1) {
        p1 += __shfl_xor_sync(0xffffffffu, p1, off);
        p2 += __shfl_xor_sync(0xffffffffu, p2, off);
    }
    if (lane == 0) { g_e1[row] = p1; g_e2[row] = p2; }
}

// ---------------- kernel 3: global max of e2 ----------------
__global__ __launch_bounds__(1024) void maxe2_kernel() {
    __shared__ float sm[32];
    const int tid = threadIdx.x;
    float v = -3.4e38f;
    for (int k = tid; k < NND; k += 1024) v = fmaxf(v, g_e2[k]);
#pragma unroll
    for (int off = 16; off > 0; off >>= 1)
        v = fmaxf(v, __shfl_xor_sync(0xffffffffu, v, off));
    if ((tid & 31) == 0) sm[tid >> 5] = v;
    __syncthreads();
    if (tid < 32) {
        v = sm[tid];
#pragma unroll
        for (int off = 16; off > 0; off >>= 1)
            v = fmaxf(v, __shfl_xor_sync(0xffffffffu, v, off));
        if (tid == 0) g_maxe2 = v;
    }
}

// ---------------- kernel 3b: per-j softmax factors (Q_j, D_j) ----------------
__global__ __launch_bounds__(256) void fbd_kernel() {
    const int j = blockIdx.x * 256 + threadIdx.x;
    const float d = g_e2[j] - g_maxe2;
    g_fBD[j] = make_float2(__expf(d), __expf(ALPHA * d));
}

// ---------------- kernel 3c: build B fragments (split-bf16, HMMA layout) ---
// Mapping (with j-permutation so A-side adj loads are contiguous int4):
//   MMA k-index c in block jblk corresponds to j = jblk*16 + perm(c),
//   perm(2q+d) = 4q+d, perm(2q+8+d) = 4q+2+d   (q = lane%4, d in {0,1}).
// Lane (q = lane&3, nr = lane>>2), col n = nb*8 + nr:
//   b0 = (h[j0+4q][n], h[j0+4q+1][n]),  b1 = (h[j0+4q+2][n], h[j0+4q+3][n]).
__global__ __launch_bounds__(256) void hfrag_kernel() {
    const int idx  = blockIdx.x * 256 + threadIdx.x;  // jblk*256 + nb*32 + lane
    const int lane = idx & 31;
    const int nb   = (idx >> 5) & 7;
    const int jblk = idx >> 8;
    const int q    = lane & 3;
    const int nr   = lane >> 2;
    const int n    = nb * 8 + nr;
    const int j0   = jblk * 16 + 4 * q;

    float v0 = g_h[(long)(j0 + 0) * F + n];
    float v1 = g_h[(long)(j0 + 1) * F + n];
    float v2 = g_h[(long)(j0 + 2) * F + n];
    float v3 = g_h[(long)(j0 + 3) * F + n];

    u32 b0h = cvt2(v0, v1);
    u32 b1h = cvt2(v2, v3);
    u32 b0l = cvt2(v0 - bflo(b0h), v1 - bfhi(b0h));
    u32 b1l = cvt2(v2 - bflo(b1h), v3 - bfhi(b1h));
    g_hB[idx] = make_uint4(b0h, b1h, b0l, b1l);
}

// ---------------- kernel 4: HMMA masked-softmax aggregate ----------------
// 256 CTAs (64 row-blocks x 4 j-splits), 256 threads, no smem/barriers.
// Warp w owns rows i0 + w*16 .. +15; lane q=lane&3, r0=lane>>2.
// Per kstep: adj int4 x2 (prefetched), fac float4 x2, w gen (factorized,
// masked), split to bf16 hi/lo A-frags, 8 n-blocks x 3 mma.sync.
__global__ __launch_bounds__(256, 2) void hmma_agg_kernel(const int* __restrict__ adj) {
    const int tid  = threadIdx.x;
    const int wid  = tid >> 5;
    const int lane = tid & 31;
    const int q    = lane & 3;
    const int r0   = lane >> 2;
    const int s    = blockIdx.x & (JSPLIT - 1);
    const int i0   = (blockIdx.x >> 2) * 128;
    const int jbase = s * KRANGE;

    const int row0 = i0 + wid * 16 + r0;
    const int row1 = row0 + 8;

    // per-row softmax constants
    const float mx = g_maxe2;
    float e1a = g_e1[row0], e1b = g_e1[row1];
    float t0 = e1a + mx, t1 = e1b + mx;
    float m0 = fmaxf(t0, ALPHA * t0), m1 = fmaxf(t1, ALPHA * t1);
    const float P0 = __expf(t0 - m0), C0 = __expf(ALPHA * t0 - m0);
    const float P1 = __expf(t1 - m1), C1 = __expf(ALPHA * t1 - m1);

    const int4* a0p = (const int4*)(adj + (long)row0 * NND + jbase) + q;
    const int4* a1p = (const int4*)(adj + (long)row1 * NND + jbase) + q;
    const uint4* bbase = g_hB + ((long)(jbase >> 4)) * 256 + lane;

    float acc[8][4];
#pragma unroll
    for (int nb = 0; nb < 8; nb++)
#pragma unroll
        for (int c = 0; c < 4; c++) acc[nb][c] = 0.0f;
    float z0 = 0.0f, z1 = 0.0f;

    int4 av0 = __ldcs(a0p);
    int4 av1 = __ldcs(a1p);

    for (int t = 0; t < KSTEPS; t++) {
        const int4 c0 = av0, c1 = av1;
        if (t + 1 < KSTEPS) {                 // prefetch next kstep's adj
            av0 = __ldcs(a0p + (t + 1) * 4);
            av1 = __ldcs(a1p + (t + 1) * 4);
        }

        const int jq = jbase + t * 16 + 4 * q;
        const float4 f01 = *(const float4*)(g_fBD + jq);      // (Q0,D0,Q1,D1)
        const float4 f23 = *(const float4*)(g_fBD + jq + 2);  // (Q2,D2,Q3,D3)

        float w00 = c0.x ? fmaxf(P0 * f01.x, C0 * f01.y) : 0.0f;
        float w01 = c0.y ? fmaxf(P0 * f01.z, C0 * f01.w) : 0.0f;
        float w02 = c0.z ? fmaxf(P0 * f23.x, C0 * f23.y) : 0.0f;
        float w03 = c0.w ? fmaxf(P0 * f23.z, C0 * f23.w) : 0.0f;
        float w10 = c1.x ? fmaxf(P1 * f01.x, C1 * f01.y) : 0.0f;
        float w11 = c1.y ? fmaxf(P1 * f01.z, C1 * f01.w) : 0.0f;
        float w12 = c1.z ? fmaxf(P1 * f23.x, C1 * f23.y) : 0.0f;
        float w13 = c1.w ? fmaxf(P1 * f23.z, C1 * f23.w) : 0.0f;

        z0 += (w00 + w01) + (w02 + w03);
        z1 += (w10 + w11) + (w12 + w13);

        // A fragments: a0=(r0,klo) a1=(r1,klo) a2=(r0,khi) a3=(r1,khi)
        u32 a0h = cvt2(w00, w01), a1h = cvt2(w10, w11);
        u32 a2h = cvt2(w02, w03), a3h = cvt2(w12, w13);
        u32 a0l = cvt2(w00 - bflo(a0h), w01 - bfhi(a0h));
        u32 a1l = cvt2(w10 - bflo(a1h), w11 - bfhi(a1h));
        u32 a2l = cvt2(w02 - bflo(a2h), w03 - bfhi(a2h));
        u32 a3l = cvt2(w12 - bflo(a3h), w13 - bfhi(a3h));

        const uint4* bb = bbase + (long)t * 256;
#pragma unroll
        for (int nb = 0; nb < 8; nb++) {
            uint4 b = __ldg(bb + nb * 32);
            mma_bf16(acc[nb], a0h, a1h, a2h, a3h, b.x, b.y);  // Ahi*Bhi
            mma_bf16(acc[nb], a0h, a1h, a2h, a3h, b.z, b.w);  // Ahi*Blo
            mma_bf16(acc[nb], a0l, a1l, a2l, a3l, b.x, b.y);  // Alo*Bhi
        }
    }

    // Z reduce across q (lanes sharing r0)
    z0 += __shfl_xor_sync(0xffffffffu, z0, 1);
    z0 += __shfl_xor_sync(0xffffffffu, z0, 2);
    z1 += __shfl_xor_sync(0xffffffffu, z1, 1);
    z1 += __shfl_xor_sync(0xffffffffu, z1, 2);
    if (q == 0) {
        g_zpart[s * NND + row0] = z0;
        g_zpart[s * NND + row1] = z1;
    }

    // write D partials: d0,d1 -> row0 cols nb*8+2q..+1 ; d2,d3 -> row1
    float* p0 = g_part + ((long)s * NND + row0) * F + 2 * q;
    float* p1 = g_part + ((long)s * NND + row1) * F + 2 * q;
#pragma unroll
    for (int nb = 0; nb < 8; nb++) {
        *(float2*)(p0 + nb * 8) = make_float2(acc[nb][0], acc[nb][1]);
        *(float2*)(p1 + nb * 8) = make_float2(acc[nb][2], acc[nb][3]);
    }
}

// ---------------- kernel 5: combine splits, normalize, ELU ----------------
__global__ __launch_bounds__(256) void combine_kernel(float* __restrict__ out) {
    const int t = blockIdx.x * 256 + threadIdx.x;
    const int i = t >> 6;
    float acc = 0.0f, z = 0.0f;
#pragma unroll
    for (int s = 0; s < JSPLIT; s++) {
        acc += g_part[(long)s * NND * F + t];
        z   += g_zpart[s * NND + i];
    }
    float o = acc / z;
    out[t] = (o > 0.0f) ? o : expm1f(o);
}

// ---------------- launch ----------------
extern "C" void kernel_launch(void* const* d_in, const int* in_sizes, int n_in,
                              void* d_out, int out_size) {
    const float* x   = (const float*)d_in[0];
    const int*   adj = (const int*)  d_in[1];
    const float* W   = (const float*)d_in[2];
    const float* a   = (const float*)d_in[3];
    float* out = (float*)d_out;

    gemm_h_kernel<<<NND / 64, 256>>>(x, W);
    e12_kernel<<<NND / 8, 256>>>(a);
    maxe2_kernel<<<1, 1024>>>();
    fbd_kernel<<<NND / 256, 256>>>();
    hfrag_kernel<<<NJBLK, 256>>>();
    hmma_agg_kernel<<<(NND / 128) * JSPLIT, 256>>>(adj);
    combine_kernel<<<(NND * F) / 256, 256>>>(out);
}